// round 9
// baseline (speedup 1.0000x reference)
#include <cuda_runtime.h>
#include <cstdint>

// StochasticPool2d: x (16,96,224,224) f32, 2x2 non-overlapping windows.
// Reference: jax.random.categorical(key(42), window_vals) == Gumbel-max with
// threefry-2x32 (partitionable counter mode); output = sampled window value.
//
// B=16 C=96 H=224 W=224 -> OH=OW=112
// N_windows = 19,267,584 ; threads = N_windows/2 = 9,633,792 = 37632*256.
//
// R7/R8: alu pipe is the binder. Rewrite each threefry rotation as a widening
// multiply by 2^r (IMAD.WIDE on the fma pipe) and fuse the rotate-combine
// with the round XOR into ONE LOP3:  x1 = (lo | hi) ^ x0.
// Per round: {IADD3, SHF, LOP3} (3 alu) -> {IADD3, IMAD.WIDE, LOP3} (2 alu + 1 fma).
// Multipliers are opaque (one = blockDim.x>>8 == 1) so ptxas cannot
// strength-reduce the multiply back into shifts.

static constexpr uint32_t TF_K1 = 42u;
static constexpr uint32_t TF_K2 = 0x1BD11BDAu ^ 0u ^ 42u;  // ks[2]

struct Rots {  // 2^r for the 8 distinct threefry-2x32 rotations, opaque to ptxas
    uint32_t m13, m15, m26, m6, m17, m29, m16, m24;
};

// rotl(x,r) ^ z  ==  (lo|hi of x*2^r) ^ z  -> IMAD.WIDE + single LOP3
__device__ __forceinline__ uint32_t rotxor(uint32_t x, uint32_t m, uint32_t z) {
    uint64_t p = (uint64_t)x * (uint64_t)m;
    uint32_t lo = (uint32_t)p;
    uint32_t hi = (uint32_t)(p >> 32);
    return (lo | hi) ^ z;
}

// threefry2x32, key=(0,42), counter=(0, n); returns out0 ^ out1.
__device__ __forceinline__ uint32_t threefry_bits(uint32_t n, const Rots& R) {
    uint32_t x0 = 0u;        // counter_hi + ks[0] (both 0)
    uint32_t x1 = n + TF_K1; // counter_lo + ks[1]
#define TF_ROUND(m) { x0 += x1; x1 = rotxor(x1, (m), x0); }
    TF_ROUND(R.m13) TF_ROUND(R.m15) TF_ROUND(R.m26) TF_ROUND(R.m6)
    x0 += TF_K1;        x1 += TF_K2 + 1u;
    TF_ROUND(R.m17) TF_ROUND(R.m29) TF_ROUND(R.m16) TF_ROUND(R.m24)
    x0 += TF_K2;        x1 += 0u + 2u;
    TF_ROUND(R.m13) TF_ROUND(R.m15) TF_ROUND(R.m26) TF_ROUND(R.m6)
    /* ks[0]=0 */       x1 += TF_K1 + 3u;
    TF_ROUND(R.m17) TF_ROUND(R.m29) TF_ROUND(R.m16) TF_ROUND(R.m24)
    x0 += TF_K1;        x1 += TF_K2 + 4u;
    TF_ROUND(R.m13) TF_ROUND(R.m15) TF_ROUND(R.m26) TF_ROUND(R.m6)
    x0 += TF_K2;        x1 += 0u + 5u;
#undef TF_ROUND
    return x0 ^ x1;
}

// bits -> uniform(tiny,1), matching jax _uniform in f32 exactly.
__device__ __forceinline__ float uniform32(uint32_t bits) {
    float f = __uint_as_float((bits >> 9) | 0x3f800000u) - 1.0f;
    return fmaxf(f, 1.17549435e-38f);
}

// Exact gumbel (matches XLA f32: precise logf == __nv_logf).
__device__ __forceinline__ float gumbel_exact(float u) {
    return -logf(-logf(u));
}

__device__ __forceinline__ float rcp_approx(float x) {
    float r;
    asm("rcp.approx.f32 %0, %1;" : "=f"(r) : "f"(x));
    return r;
}

// One 2x2 window: fast gumbel-max with certified margin, exact fallback.
// With u in [tiny, 1-2^-24], t = -log u in [1.19e-7, 88.8], |g| <= 17, so the
// fast-vs-exact per-value error is bounded by 1.8e-5 + 1e-6/min_t. Certify if
// min_t >= 1e-3 and margin > 8e-5 + 4e-6/min_t (>= 2x bound + rcp slop).
__device__ __forceinline__ float pool_window(float v0, float v1, float v2, float v3,
                                             float u0, float u1, float u2, float u3) {
    float t0 = -__logf(u0), t1 = -__logf(u1), t2 = -__logf(u2), t3 = -__logf(u3);
    float g0 = -__logf(t0), g1 = -__logf(t1), g2 = -__logf(t2), g3 = -__logf(t3);
    float s0 = v0 + g0, s1 = v1 + g1, s2 = v2 + g2, s3 = v3 + g3;

    // first-max scan with second-max tracking
    float best = s0, second = -3.4e38f, val = v0;
    if (s1 > best) { second = best; best = s1; val = v1; } else second = s1;
    if (s2 > best) { second = best; best = s2; val = v2; }
    else if (s2 > second) second = s2;
    if (s3 > best) { second = best; best = s3; val = v3; }
    else if (s3 > second) second = s3;

    float min_t = fminf(fminf(t0, t1), fminf(t2, t3));
    float E = fmaf(rcp_approx(min_t), 4e-6f, 8e-5f);

    bool certain = (min_t >= 1e-3f) && (best - second > E);
    if (!certain) {
        // Bit-exact reference path (rare).
        float G0 = gumbel_exact(u0), G1 = gumbel_exact(u1);
        float G2 = gumbel_exact(u2), G3 = gumbel_exact(u3);
        float S0 = v0 + G0, S1 = v1 + G1, S2 = v2 + G2, S3 = v3 + G3;
        float B = S0; val = v0;
        if (S1 > B) { B = S1; val = v1; }
        if (S2 > B) { B = S2; val = v2; }
        if (S3 > B) { B = S3; val = v3; }
    }
    return val;
}

__global__ void __launch_bounds__(256)
stochpool_kernel(const float* __restrict__ x, float* __restrict__ out) {
    uint32_t i = blockIdx.x * 256u + threadIdx.x;  // grid covers range exactly

    // Opaque 1 -> multipliers 2^r ptxas cannot constant-fold into shifts.
    uint32_t one = blockDim.x >> 8;  // == 1
    Rots R;
    R.m13 = one << 13; R.m15 = one << 15; R.m26 = one << 26; R.m6  = one << 6;
    R.m17 = one << 17; R.m29 = one << 29; R.m16 = one << 16; R.m24 = one << 24;

    // Thread i handles windows 2i, 2i+1 (adjacent in ow; OW=112 even).
    uint32_t owp = i % 56u;
    uint32_t t   = i / 56u;
    uint32_t oh  = t % 112u;
    uint32_t bc  = t / 112u;  // b*96 + c

    uint32_t in_base = (bc * 224u + 2u * oh) * 224u + 4u * owp;
    float4 r0 = *reinterpret_cast<const float4*>(x + in_base);
    float4 r1 = *reinterpret_cast<const float4*>(x + in_base + 224u);

    // Window w uses gumbel counters 4w..4w+3 -> this thread: 8i..8i+7.
    uint32_t cbase = 8u * i;
    float u[8];
#pragma unroll
    for (int k = 0; k < 8; k++)
        u[k] = uniform32(threefry_bits(cbase + (uint32_t)k, R));

    // window k-index = kh*2+kw -> (r.x, r.y of row0; r.x, r.y of row1)
    float o0 = pool_window(r0.x, r0.y, r1.x, r1.y, u[0], u[1], u[2], u[3]);
    float o1 = pool_window(r0.z, r0.w, r1.z, r1.w, u[4], u[5], u[6], u[7]);

    uint32_t out_base = (bc * 112u + oh) * 112u + 2u * owp;
    *reinterpret_cast<float2*>(out + out_base) = make_float2(o0, o1);
}

extern "C" void kernel_launch(void* const* d_in, const int* in_sizes, int n_in,
                              void* d_out, int out_size) {
    const float* x = (const float*)d_in[0];
    float* out = (float*)d_out;
    (void)in_sizes; (void)n_in; (void)out_size;
    stochpool_kernel<<<37632, 256>>>(x, out);
}

// round 11
// speedup vs baseline: 1.2483x; 1.2483x over previous
#include <cuda_runtime.h>
#include <cstdint>

// StochasticPool2d: x (16,96,224,224) f32, 2x2 non-overlapping windows.
// Reference: jax.random.categorical(key(42), window_vals) == Gumbel-max with
// threefry-2x32 (partitionable counter mode); output = sampled window value.
//
// B=16 C=96 H=224 W=224 -> OH=OW=112
// N_windows = 19,267,584 ; threads = N_windows/2 = 9,633,792 = 37632*256.
//
// R9/R10 = R5-best (plain SHF threefry, fast log path + certified margin,
// bit-exact fallback) + micro-cuts on the binding alu pipe:
//  - base-2 scoring: s = v - ln2*lg2(-lg2 u) + const  (2 MUFU + 1 FFMA/value)
//  - uniform construction via mad.hi.u32(bits, 2^23, 0x3f800000) (1 fma op
//    replaces SHF+LOP3; OR==ADD because the exponent constant's low 23 bits
//    are zero). m23 is opaque so ptxas can't strength-reduce to a shift.

static constexpr uint32_t TF_K1 = 42u;
static constexpr uint32_t TF_K2 = 0x1BD11BDAu ^ 0u ^ 42u;  // ks[2]

__device__ __forceinline__ uint32_t rotl32(uint32_t x, int d) {
    return __funnelshift_l(x, x, d);
}

// threefry2x32, key=(0,42), counter=(0, n); returns out0 ^ out1.
__device__ __forceinline__ uint32_t threefry_bits(uint32_t n) {
    uint32_t x0 = 0u;        // counter_hi + ks[0] (both 0)
    uint32_t x1 = n + TF_K1; // counter_lo + ks[1]
#define TF_ROUND(r) { x0 += x1; x1 = rotl32(x1, (r)); x1 ^= x0; }
    TF_ROUND(13) TF_ROUND(15) TF_ROUND(26) TF_ROUND(6)
    x0 += TF_K1;        x1 += TF_K2 + 1u;
    TF_ROUND(17) TF_ROUND(29) TF_ROUND(16) TF_ROUND(24)
    x0 += TF_K2;        x1 += 0u + 2u;
    TF_ROUND(13) TF_ROUND(15) TF_ROUND(26) TF_ROUND(6)
    /* ks[0]=0 */       x1 += TF_K1 + 3u;
    TF_ROUND(17) TF_ROUND(29) TF_ROUND(16) TF_ROUND(24)
    x0 += TF_K1;        x1 += TF_K2 + 4u;
    TF_ROUND(13) TF_ROUND(15) TF_ROUND(26) TF_ROUND(6)
    x0 += TF_K2;        x1 += 0u + 5u;
#undef TF_ROUND
    return x0 ^ x1;
}

// (bits>>9) | 0x3f800000  as one IMAD.HI on the fma pipe:
// umulhi(bits, 2^23) = bits>>9, and +0x3f800000 == OR (low 23 bits are 0).
__device__ __forceinline__ uint32_t expbits(uint32_t bits, uint32_t m23, uint32_t c) {
    uint32_t d;
    asm("mad.hi.u32 %0, %1, %2, %3;" : "=r"(d) : "r"(bits), "r"(m23), "r"(c));
    return d;
}

// bits -> uniform(tiny,1), matching jax _uniform in f32 exactly.
__device__ __forceinline__ float uniform32(uint32_t bits, uint32_t m23, uint32_t c) {
    float f = __uint_as_float(expbits(bits, m23, c)) - 1.0f;
    return fmaxf(f, 1.17549435e-38f);
}

// Exact gumbel (matches XLA f32: precise logf == __nv_logf).
__device__ __forceinline__ float gumbel_exact(float u) {
    return -logf(-logf(u));
}

__device__ __forceinline__ float rcp_approx(float x) {
    float r;
    asm("rcp.approx.f32 %0, %1;" : "=f"(r) : "f"(x));
    return r;
}

// One 2x2 window. Fast path in base 2:
//   L = -lg2(u) in (0, 127];  exact score (up to a shared constant ln(ln2)):
//   s* = v - ln2*lg2(L).  Fast: s = v - ln2*__log2f(-__log2f(u)).
// MUFU.LG2 error <= ~4e-6 abs on each log (result magnitudes <= ~9 here), and
// d lg2(L) <= errL/(L ln2), so |s - s*| <= ~3e-5 + 4e-6/min_L. Certify when
// min_L >= 2e-3 and top1-top2 margin > 8e-5 + 1e-5/min_L (>= 2x bound + rcp
// slop); otherwise recompute bit-exactly via logf.
__device__ __forceinline__ float pool_window(float v0, float v1, float v2, float v3,
                                             float u0, float u1, float u2, float u3) {
    const float NLN2 = -0.69314718055994531f;
    float l0 = __log2f(u0), l1 = __log2f(u1), l2 = __log2f(u2), l3 = __log2f(u3);
    float m0 = __log2f(-l0), m1 = __log2f(-l1), m2 = __log2f(-l2), m3 = __log2f(-l3);
    float s0 = fmaf(NLN2, m0, v0), s1 = fmaf(NLN2, m1, v1);
    float s2 = fmaf(NLN2, m2, v2), s3 = fmaf(NLN2, m3, v3);

    // first-max scan with second-max tracking
    float best = s0, second = -3.4e38f, val = v0;
    if (s1 > best) { second = best; best = s1; val = v1; } else second = s1;
    if (s2 > best) { second = best; best = s2; val = v2; }
    else if (s2 > second) second = s2;
    if (s3 > best) { second = best; best = s3; val = v3; }
    else if (s3 > second) second = s3;

    float minL = -fmaxf(fmaxf(l0, l1), fmaxf(l2, l3));  // min of -lg2(u)
    float E = fmaf(rcp_approx(minL), 1e-5f, 8e-5f);

    bool certain = (minL >= 2e-3f) && (best - second > E);
    if (!certain) {
        // Bit-exact reference path (rare, ~0.6%).
        float G0 = gumbel_exact(u0), G1 = gumbel_exact(u1);
        float G2 = gumbel_exact(u2), G3 = gumbel_exact(u3);
        float S0 = v0 + G0, S1 = v1 + G1, S2 = v2 + G2, S3 = v3 + G3;
        float B = S0; val = v0;
        if (S1 > B) { B = S1; val = v1; }
        if (S2 > B) { B = S2; val = v2; }
        if (S3 > B) { B = S3; val = v3; }
    }
    return val;
}

__global__ void __launch_bounds__(256)
stochpool_kernel(const float* __restrict__ x, float* __restrict__ out) {
    uint32_t i = blockIdx.x * 256u + threadIdx.x;  // grid covers range exactly

    uint32_t one = blockDim.x >> 8;     // == 1, opaque to ptxas
    uint32_t m23 = one << 23;           // multiplier for IMAD.HI (>>9)
    uint32_t c3f8 = 0x3f800000u * one;  // exponent constant in a register

    // Thread i handles windows 2i, 2i+1 (adjacent in ow; OW=112 even).
    uint32_t owp = i % 56u;
    uint32_t t   = i / 56u;
    uint32_t oh  = t % 112u;
    uint32_t bc  = t / 112u;  // b*96 + c

    uint32_t in_base = (bc * 224u + 2u * oh) * 224u + 4u * owp;
    float4 r0 = *reinterpret_cast<const float4*>(x + in_base);
    float4 r1 = *reinterpret_cast<const float4*>(x + in_base + 224u);

    // Window w uses gumbel counters 4w..4w+3 -> this thread: 8i..8i+7.
    uint32_t cbase = 8u * i;
    float u[8];
#pragma unroll
    for (int k = 0; k < 8; k++)
        u[k] = uniform32(threefry_bits(cbase + (uint32_t)k), m23, c3f8);

    // window k-index = kh*2+kw -> (r.x, r.y of row0; r.x, r.y of row1)
    float o0 = pool_window(r0.x, r0.y, r1.x, r1.y, u[0], u[1], u[2], u[3]);
    float o1 = pool_window(r0.z, r0.w, r1.z, r1.w, u[4], u[5], u[6], u[7]);

    uint32_t out_base = (bc * 112u + oh) * 112u + 2u * owp;
    *reinterpret_cast<float2*>(out + out_base) = make_float2(o0, o1);
}

extern "C" void kernel_launch(void* const* d_in, const int* in_sizes, int n_in,
                              void* d_out, int out_size) {
    const float* x = (const float*)d_in[0];
    float* out = (float*)d_out;
    (void)in_sizes; (void)n_in; (void)out_size;
    stochpool_kernel<<<37632, 256>>>(x, out);
}